// round 2
// baseline (speedup 1.0000x reference)
#include <cuda_runtime.h>
#include <cuda_bf16.h>

#define FULLMASK 0xffffffffu

constexpr int   B_     = 256;
constexpr int   T_     = 256;
constexpr int   C_     = 1024;
constexpr int   L_     = 32;
constexpr int   S_     = 65;      // 2*L+1
constexpr int   SP_    = 34;      // compact row: [blank, lab0..lab31, pad0]
constexpr int   BLANK_ = C_ - 1;
constexpr float PRE    = 512.0f;  // 2^9 per-step prescale
constexpr int   PRE_E  = 9;
constexpr float EPS    = 1e-7f;
constexpr float EPS_S  = EPS * PRE;

// compact gathered probabilities: scr[b][t][k] = 512*(p[b,t,cls_k] + eps)
// k=0 -> blank, k=1..32 -> labels, k=33 -> 0 (dummy-state pad)
__device__ float g_scr[(size_t)B_ * T_ * SP_];

// ---------------------------------------------------------------------------
// Phase 1: massively parallel gather. One warp per (b,t) row.
// ---------------------------------------------------------------------------
__global__ __launch_bounds__(256)
void ctc_gather_kernel(const int* __restrict__ y_true,
                       const float* __restrict__ y_pred)
{
    const int gw   = (blockIdx.x * blockDim.x + threadIdx.x) >> 5; // row id
    const int lane = threadIdx.x & 31;
    if (gw >= B_ * T_) return;
    const int b = gw >> 8;                     // T_ == 256

    const int lab = __ldg(y_true + b * L_ + lane);     // coalesced (1 line)
    const float* rp = y_pred + (size_t)gw * C_;
    const float  q  = __ldg(rp + lab);                 // scattered gather

    float* orow = g_scr + (size_t)gw * SP_;
    orow[1 + lane] = fmaf(q, PRE, EPS_S);              // coalesced store
    if (lane == 0) {
        const float qb = __ldg(rp + BLANK_);
        orow[0]  = fmaf(qb, PRE, EPS_S);
        orow[33] = 0.0f;
    }
}

// ---------------------------------------------------------------------------
// Phase 2: serial forward scan, one warp per batch element.
// 3 extended states per lane (lanes 0..21 hold s=0..65; s=65 dummy).
// Linear domain with exact power-of-2 renorm every 8 steps.
// ---------------------------------------------------------------------------
__device__ __forceinline__ int kidx(int s) {
    // compact-row index for extended state s
    return (s >= S_) ? 33 : ((s & 1) ? ((s >> 1) + 1) : 0);
}

__global__ __launch_bounds__(64, 1)
void ctc_scan_kernel(const int* __restrict__ y_true,
                     float* __restrict__ out)
{
    const int lane = threadIdx.x & 31;
    const int b    = blockIdx.x * 2 + (threadIdx.x >> 5); // 128 blocks x 2 warps

    const int lab = y_true[b * L_ + lane];
    const unsigned nzm = __ballot_sync(FULLMASK, lab != 0);
    const int len = __popc(nzm);

    const int s0 = 3 * lane, s1 = s0 + 1, s2 = s0 + 2;
    const int k0 = kidx(s0), k1 = kidx(s1), k2 = kidx(s2);

    // skip-allow flags (odd states only, label[j] != label[j-1] or j==0)
    float al0, al1, al2;
#define ALLOW_SETUP(s, al) {                                        \
        int j  = ((s) - 1) >> 1;                                    \
        j = j < 0 ? 0 : (j > 31 ? 31 : j);                          \
        int jm = j > 0 ? j - 1 : 0;                                 \
        int lj = __shfl_sync(FULLMASK, lab, j);                     \
        int lm = __shfl_sync(FULLMASK, lab, jm);                    \
        al = (((s) & 1) && ((s) < S_) && (j == 0 || lj != lm)) ? 1.0f : 0.0f; \
    }
    ALLOW_SETUP(s0, al0);
    ALLOW_SETUP(s1, al1);
    ALLOW_SETUP(s2, al2);
#undef ALLOW_SETUP

    const float* scr_b = g_scr + (size_t)b * T_ * SP_;

    // t = 0 init (values already scaled by 2^9): alpha[0], alpha[1]
    float r0 = 0.0f, r1 = 0.0f, r2 = 0.0f;
    if (lane == 0) {
        r0 = scr_b[0];      // k(0) = 0 (blank)
        r1 = scr_b[1];      // k(1) = 1 (label 0)
    }

    // depth-8 register prefetch of compact rows t=1..8
    float pa[8], pb[8], pc[8];
#pragma unroll
    for (int j = 0; j < 8; ++j) {
        const float* rp = scr_b + (size_t)(1 + j) * SP_;
        pa[j] = __ldg(rp + k0);
        pb[j] = __ldg(rp + k1);
        pc[j] = __ldg(rp + k2);
    }

    int Eacc = 0;

    for (int tb = 1; tb < T_; tb += 8) {
#pragma unroll
        for (int j = 0; j < 8; ++j) {
            const int t = tb + j;
            if (t < T_) {
                const float p0 = pa[j], p1 = pb[j], p2 = pc[j];

                const int tp = t + 8;
                if (tp < T_) {
                    const float* rp = scr_b + (size_t)tp * SP_;
                    pa[j] = __ldg(rp + k0);
                    pb[j] = __ldg(rp + k1);
                    pc[j] = __ldg(rp + k2);
                }

                float u1 = __shfl_up_sync(FULLMASK, r1, 1);
                float u2 = __shfl_up_sync(FULLMASK, r2, 1);
                if (lane == 0) { u1 = 0.0f; u2 = 0.0f; }

                const float n0 = p0 * fmaf(al0, u1, r0 + u2);
                const float n1 = p1 * fmaf(al1, u2, r1 + r0);
                const float n2 = p2 * fmaf(al2, r0, r2 + r1);
                r0 = n0; r1 = n1; r2 = n2;

                if ((t & 7) == 0) {
                    float m = fmaxf(fmaxf(r0, r1), r2);
#pragma unroll
                    for (int o = 16; o; o >>= 1)
                        m = fmaxf(m, __shfl_xor_sync(FULLMASK, m, o));
                    const int e = (__float_as_int(m) >> 23) - 127;
                    const float sc = __int_as_float((127 - e) << 23); // exact 2^-e
                    r0 *= sc; r1 *= sc; r2 *= sc;
                    Eacc += e;
                }
            }
        }
    }

    // loss = -logaddexp(alpha[2*len], alpha[2*len-1])
    int ilb = 2 * len;
    int ill = 2 * len - 1;
    if (ill < 0) ill += S_;

    const int lbL = ilb / 3, lbR = ilb % 3;
    const int llL = ill / 3, llR = ill % 3;
    const float g0 = __shfl_sync(FULLMASK, r0, lbL);
    const float g1 = __shfl_sync(FULLMASK, r1, lbL);
    const float g2 = __shfl_sync(FULLMASK, r2, lbL);
    const float h0 = __shfl_sync(FULLMASK, r0, llL);
    const float h1 = __shfl_sync(FULLMASK, r1, llL);
    const float h2 = __shfl_sync(FULLMASK, r2, llL);
    const float vlb = (lbR == 0) ? g0 : ((lbR == 1) ? g1 : g2);
    const float vll = (llR == 0) ? h0 : ((llR == 1) ? h1 : h2);

    if (lane == 0) {
        const float LN2 = 0.6931471805599453f;
        // stored = true * 2^(PRE_E*T) * 2^(-Eacc)
        float logsum = logf(vlb + vll) + (float)(Eacc - PRE_E * T_) * LN2;
        out[b] = -logsum;
    }
}

extern "C" void kernel_launch(void* const* d_in, const int* in_sizes, int n_in,
                              void* d_out, int out_size)
{
    (void)n_in; (void)out_size;
    const int*   y_true;
    const float* y_pred;
    if (in_sizes[0] == B_ * L_) {
        y_true = (const int*)d_in[0];
        y_pred = (const float*)d_in[1];
    } else {
        y_true = (const int*)d_in[1];
        y_pred = (const float*)d_in[0];
    }

    // Phase 1: 65536 row-warps, 8 warps per block
    ctc_gather_kernel<<<(B_ * T_) / 8, 256>>>(y_true, y_pred);
    // Phase 2: 256 scan warps, 2 per block
    ctc_scan_kernel<<<B_ / 2, 64>>>(y_true, (float*)d_out);
}

// round 3
// speedup vs baseline: 3.1611x; 3.1611x over previous
#include <cuda_runtime.h>

#define FULLMASK 0xffffffffu

constexpr int   B_     = 256;
constexpr int   T_     = 256;
constexpr int   C_     = 1024;
constexpr int   L_     = 32;
constexpr int   S_     = 65;      // 2*L+1 extended states
constexpr int   SP_    = 34;      // compact row: [blank, lab0..lab31, pad0]
constexpr int   BLANK_ = C_ - 1;
constexpr float PRE    = 512.0f;  // 2^9 per-step prescale
constexpr int   PRE_E  = 9;
constexpr float EPS    = 1e-7f;
constexpr float EPS_S  = EPS * PRE;

__device__ __forceinline__ int kidx(int s) {
    return (s >= S_) ? 33 : ((s & 1) ? ((s >> 1) + 1) : 0);
}

// fwd skip: into s from s-2 (s odd, label[j] != label[j-1] or j==0)
__device__ __forceinline__ float allow_fwd(int s, const int* labs) {
    if (!(s & 1) || s >= S_) return 0.0f;
    const int j = (s - 1) >> 1;
    return (j == 0 || labs[j] != labs[j - 1]) ? 1.0f : 0.0f;
}
// bwd skip: into s from s+2 (s odd, s+2 <= S-1, label[(s+1)/2] != label[(s-1)/2])
__device__ __forceinline__ float allow_bwd(int s, const int* labs) {
    if (!(s & 1) || (s + 2) > S_ - 1) return 0.0f;
    const int jn = (s + 1) >> 1, jp = (s - 1) >> 1;
    return (labs[jn] != labs[jp]) ? 1.0f : 0.0f;
}

// exact power-of-2 warp renorm; returns exponent removed
__device__ __forceinline__ int renorm(float& r0, float& r1, float& r2) {
    float m = fmaxf(fmaxf(r0, r1), r2);
#pragma unroll
    for (int o = 16; o; o >>= 1)
        m = fmaxf(m, __shfl_xor_sync(FULLMASK, m, o));
    const int e = (__float_as_int(m) >> 23) - 127;
    const float sc = __int_as_float((127 - e) << 23);  // 2^-e, exact
    r0 *= sc; r1 *= sc; r2 *= sc;
    return e;
}

__global__ __launch_bounds__(256, 2)
void ctc_fused_kernel(const int* __restrict__ y_true,
                      const float* __restrict__ y_pred,
                      float* __restrict__ out)
{
    __shared__ float slab[T_ * SP_];   // 34816 B, scaled probs per (t, compact-k)
    __shared__ int   labs[L_];
    __shared__ float exA[66], exB[66];
    __shared__ int   exE[2];

    const int b    = blockIdx.x;
    const int tid  = threadIdx.x;
    const int lane = tid & 31;
    const int wid  = tid >> 5;

    if (tid < L_) labs[tid] = __ldg(y_true + b * L_ + tid);
    __syncthreads();

    // ------------------ gather phase: thread tid owns row t = tid ------------
    {
        const float* rp  = y_pred + ((size_t)b * T_ + tid) * C_;
        float* orow = slab + tid * SP_;
        float v[33];
        v[0] = __ldg(rp + BLANK_);
#pragma unroll
        for (int j = 0; j < 32; ++j) v[1 + j] = __ldg(rp + labs[j]);
#pragma unroll
        for (int k = 0; k < 33; ++k) orow[k] = fmaf(v[k], PRE, EPS_S);
        orow[33] = 0.0f;   // pad: keeps dummy states at exactly 0
    }
    __syncthreads();

    // ------------------ scan phase: warp0 forward, warp1 backward ------------
    const int s0 = 3 * lane, s1 = s0 + 1, s2 = s0 + 2;
    const int k0 = kidx(s0), k1 = kidx(s1), k2 = kidx(s2);

    if (wid == 0) {
        // forward: alpha_0 .. alpha_127
        const float a0 = allow_fwd(s0, labs);
        const float a1 = allow_fwd(s1, labs);
        const float a2 = allow_fwd(s2, labs);

        float r0 = 0.0f, r1 = 0.0f, r2 = 0.0f;
        if (lane == 0) { r0 = slab[0]; r1 = slab[1]; }   // t=0 init

        float pa[4], pb[4], pc[4];
#pragma unroll
        for (int j = 0; j < 4; ++j) {
            const float* sr = slab + (1 + j) * SP_;
            pa[j] = sr[k0]; pb[j] = sr[k1]; pc[j] = sr[k2];
        }

        int Eacc = 0;
        for (int tb = 1; tb < 128; tb += 4) {
#pragma unroll
            for (int j = 0; j < 4; ++j) {
                const int t = tb + j;
                if (t < 128) {
                    const float p0 = pa[j], p1 = pb[j], p2 = pc[j];
                    const int tp = t + 4;
                    if (tp < 128) {
                        const float* sr = slab + tp * SP_;
                        pa[j] = sr[k0]; pb[j] = sr[k1]; pc[j] = sr[k2];
                    }
                    float u1 = __shfl_up_sync(FULLMASK, r1, 1);
                    float u2 = __shfl_up_sync(FULLMASK, r2, 1);
                    if (lane == 0) { u1 = 0.0f; u2 = 0.0f; }
                    const float n0 = p0 * fmaf(a0, u1, r0 + u2);
                    const float n1 = p1 * fmaf(a1, u2, r1 + r0);
                    const float n2 = p2 * fmaf(a2, r0, r2 + r1);
                    r0 = n0; r1 = n1; r2 = n2;
                    if ((t & 7) == 0) Eacc += renorm(r0, r1, r2);
                }
            }
        }
        if (lane < 22) { exA[s0] = r0; exA[s1] = r1; exA[s2] = r2; }
        if (lane == 0) exE[0] = Eacc;
    }
    else if (wid == 1) {
        // backward: beta_127 via c_t = p_t * beta_t, t = 255 .. 128
        const int lab = labs[lane];
        const unsigned nzm = __ballot_sync(FULLMASK, lab != 0);
        const int len = __popc(nzm);
        int ilb = 2 * len;
        int ill = 2 * len - 1;
        if (ill < 0) ill += S_;

        const float a0 = allow_bwd(s0, labs);
        const float a1 = allow_bwd(s1, labs);
        const float a2 = allow_bwd(s2, labs);

        // init c_255[s] = p_255[s] for s in {ilb, ill}, else 0
        float r0, r1, r2;
        {
            const float* sr = slab + 255 * SP_;
            r0 = (s0 == ilb || s0 == ill) ? sr[k0] : 0.0f;
            r1 = (s1 == ilb || s1 == ill) ? sr[k1] : 0.0f;
            r2 = (s2 == ilb || s2 == ill) ? sr[k2] : 0.0f;
        }

        float pa[4], pb[4], pc[4];
#pragma unroll
        for (int j = 0; j < 4; ++j) {
            const float* sr = slab + (254 - j) * SP_;
            pa[j] = sr[k0]; pb[j] = sr[k1]; pc[j] = sr[k2];
        }

        int Eacc = 0;
        for (int tb = 254; tb >= 128; tb -= 4) {
#pragma unroll
            for (int j = 0; j < 4; ++j) {
                const int t = tb - j;
                if (t >= 128) {
                    const float p0 = pa[j], p1 = pb[j], p2 = pc[j];
                    const int tm = t - 4;
                    if (tm >= 128) {
                        const float* sr = slab + tm * SP_;
                        pa[j] = sr[k0]; pb[j] = sr[k1]; pc[j] = sr[k2];
                    }
                    const float u0 = __shfl_down_sync(FULLMASK, r0, 1);
                    const float u1 = __shfl_down_sync(FULLMASK, r1, 1);
                    const float B0 = fmaf(a0, r2, r0 + r1);
                    const float B1 = fmaf(a1, u0, r1 + r2);
                    const float B2 = fmaf(a2, u1, r2 + u0);
                    r0 = p0 * B0; r1 = p1 * B1; r2 = p2 * B2;
                    if ((t & 7) == 0) Eacc += renorm(r0, r1, r2);
                }
            }
        }
        // final combine (no p multiply): beta_127 from c_128
        const float u0 = __shfl_down_sync(FULLMASK, r0, 1);
        const float u1 = __shfl_down_sync(FULLMASK, r1, 1);
        const float B0 = fmaf(a0, r2, r0 + r1);
        const float B1 = fmaf(a1, u0, r1 + r2);
        const float B2 = fmaf(a2, u1, r2 + u0);
        if (lane < 22) { exB[s0] = B0; exB[s1] = B1; exB[s2] = B2; }
        if (lane == 0) exE[1] = Eacc;
    }
    __syncthreads();

    // ------------------ combine: P = sum_s alpha_127[s] * beta_127[s] --------
    if (wid == 0) {
        float part = 0.0f;
        if (lane < 22)
            part = exA[s0] * exB[s0] + exA[s1] * exB[s1] + exA[s2] * exB[s2];
#pragma unroll
        for (int o = 16; o; o >>= 1)
            part += __shfl_xor_sync(FULLMASK, part, o);
        if (lane == 0) {
            const float LN2 = 0.6931471805599453f;
            // stored dot = P_true * PRE^T * 2^(-(Ea+Eb))
            out[b] = -(logf(part) +
                       (float)(exE[0] + exE[1] - PRE_E * T_) * LN2);
        }
    }
}

extern "C" void kernel_launch(void* const* d_in, const int* in_sizes, int n_in,
                              void* d_out, int out_size)
{
    (void)n_in; (void)out_size;
    const int*   y_true;
    const float* y_pred;
    if (in_sizes[0] == B_ * L_) {
        y_true = (const int*)d_in[0];
        y_pred = (const float*)d_in[1];
    } else {
        y_true = (const int*)d_in[1];
        y_pred = (const float*)d_in[0];
    }
    ctc_fused_kernel<<<B_, 256>>>(y_true, y_pred, (float*)d_out);
}

// round 4
// speedup vs baseline: 3.3174x; 1.0494x over previous
#include <cuda_runtime.h>

#define FULLMASK 0xffffffffu

constexpr int   B_     = 256;
constexpr int   T_     = 256;
constexpr int   C_     = 1024;
constexpr int   L_     = 32;
constexpr int   S_     = 65;      // 2*L+1 extended states
constexpr int   SP_    = 34;      // compact row: [blank, lab0..lab31, pad0]
constexpr int   BLANK_ = C_ - 1;
constexpr float PRE    = 512.0f;  // 2^9 per-step prescale
constexpr int   PRE_E  = 9;
constexpr float EPS    = 1e-7f;
constexpr float EPS_S  = EPS * PRE;

__device__ __forceinline__ int kidx(int s) {
    return (s >= S_) ? 33 : ((s & 1) ? ((s >> 1) + 1) : 0);
}
__device__ __forceinline__ float allow_fwd(int s, const int* labs) {
    if (!(s & 1) || s >= S_) return 0.0f;
    const int j = (s - 1) >> 1;
    return (j == 0 || labs[j] != labs[j - 1]) ? 1.0f : 0.0f;
}
__device__ __forceinline__ float allow_bwd(int s, const int* labs) {
    if (!(s & 1) || (s + 2) > S_ - 1) return 0.0f;
    const int jn = (s + 1) >> 1, jp = (s - 1) >> 1;
    return (labs[jn] != labs[jp]) ? 1.0f : 0.0f;
}
__device__ __forceinline__ int renorm(float& r0, float& r1, float& r2) {
    float m = fmaxf(fmaxf(r0, r1), r2);
#pragma unroll
    for (int o = 16; o; o >>= 1)
        m = fmaxf(m, __shfl_xor_sync(FULLMASK, m, o));
    const int e = (__float_as_int(m) >> 23) - 127;
    const float sc = __int_as_float((127 - e) << 23);  // exact 2^-e
    r0 *= sc; r1 *= sc; r2 *= sc;
    return e;
}
__device__ __forceinline__ float ldg_cg(const float* p) {
    float v;
    asm volatile("ld.global.cg.f32 %0, [%1];" : "=f"(v) : "l"(p));
    return v;
}

__global__ __launch_bounds__(256, 2)
void ctc_fused_kernel(const int* __restrict__ y_true,
                      const float* __restrict__ y_pred,
                      float* __restrict__ out)
{
    __shared__ float slab[T_ * SP_];     // 34816 B
    __shared__ int   labs[L_];
    __shared__ float exA[66], exB[66];
    __shared__ int   exE[2];

    const int b    = blockIdx.x;
    const int tid  = threadIdx.x;
    const int lane = tid & 31;
    const int wid  = tid >> 5;

    if (tid < L_) labs[tid] = __ldg(y_true + b * L_ + tid);
    __syncthreads();

    const float* base = y_pred + (size_t)b * T_ * C_;

    // ---- gather one stage: 32 fwd rows starting at fb, 32 bwd rows at bb ----
    auto gather_stage = [&](int fb, int bb, int t0, int nth) {
        for (int f = t0; f < 64 * 33; f += nth) {
            const int rl  = f / 33;
            const int c   = f - rl * 33;
            const int row = (rl < 32) ? (fb + rl) : (bb + rl - 32);
            const int cls = c ? labs[c - 1] : BLANK_;
            const float v = ldg_cg(base + (size_t)row * C_ + cls);
            slab[row * SP_ + c] = fmaf(v, PRE, EPS_S);
        }
        for (int r = t0; r < 64; r += nth) {
            const int row = (r < 32) ? (fb + r) : (bb + r - 32);
            slab[row * SP_ + 33] = 0.0f;   // dummy-state pad
        }
    };

    // stage 0: all 256 threads gather fwd rows 0..31, bwd rows 224..255
    gather_stage(0, 224, tid, 256);
    __syncthreads();

    // ---- persistent scan state ----
    const int s0 = 3 * lane, s1 = s0 + 1, s2 = s0 + 2;
    const int k0 = kidx(s0), k1 = kidx(s1), k2 = kidx(s2);

    // forward state (warp 0)
    const float fa0 = allow_fwd(s0, labs);
    const float fa1 = allow_fwd(s1, labs);
    const float fa2 = allow_fwd(s2, labs);
    float fr0 = 0.0f, fr1 = 0.0f, fr2 = 0.0f;
    int   fE  = 0;

    // backward state (warp 1)
    const float ba0 = allow_bwd(s0, labs);
    const float ba1 = allow_bwd(s1, labs);
    const float ba2 = allow_bwd(s2, labs);
    float br0 = 0.0f, br1 = 0.0f, br2 = 0.0f;
    int   bE  = 0;
    int   ilb = 0, ill = 0;
    {
        const int lab = labs[lane];
        const unsigned nzm = __ballot_sync(FULLMASK, lab != 0);
        const int len = __popc(nzm);
        ilb = 2 * len;
        ill = 2 * len - 1;
        if (ill < 0) ill += S_;
    }

    // ---- pipeline: iter k scans chunk k-1 while warps 2..7 gather stage k ---
    for (int k = 1; k <= 4; ++k) {
        const int q = k - 1;
        if (wid == 0) {
            // forward chunk q: t in [max(1,32q), 32q+32)
            if (q == 0 && lane == 0) { fr0 = slab[0]; fr1 = slab[1]; }
            const int tlo = (q == 0) ? 1 : 32 * q;
            const int thi = 32 * q + 32;
#pragma unroll 4
            for (int t = tlo; t < thi; ++t) {
                const float* sr = slab + t * SP_;
                const float p0 = sr[k0], p1 = sr[k1], p2 = sr[k2];
                float u1 = __shfl_up_sync(FULLMASK, fr1, 1);
                float u2 = __shfl_up_sync(FULLMASK, fr2, 1);
                if (lane == 0) { u1 = 0.0f; u2 = 0.0f; }
                const float n0 = p0 * fmaf(fa0, u1, fr0 + u2);
                const float n1 = p1 * fmaf(fa1, u2, fr1 + fr0);
                const float n2 = p2 * fmaf(fa2, fr0, fr2 + fr1);
                fr0 = n0; fr1 = n1; fr2 = n2;
                if ((t & 7) == 0) fE += renorm(fr0, fr1, fr2);
            }
            if (k == 4) {
                if (lane < 22) { exA[s0] = fr0; exA[s1] = fr1; exA[s2] = fr2; }
                if (lane == 0) exE[0] = fE;
            }
        }
        else if (wid == 1) {
            // backward chunk q: t from min(254, 255-32q) down to 224-32q
            if (q == 0) {
                const float* sr = slab + 255 * SP_;
                br0 = (s0 == ilb || s0 == ill) ? sr[k0] : 0.0f;
                br1 = (s1 == ilb || s1 == ill) ? sr[k1] : 0.0f;
                br2 = (s2 == ilb || s2 == ill) ? sr[k2] : 0.0f;
            }
            const int thi = (q == 0) ? 254 : (255 - 32 * q);
            const int tlo = 224 - 32 * q;
#pragma unroll 4
            for (int t = thi; t >= tlo; --t) {
                const float* sr = slab + t * SP_;
                const float p0 = sr[k0], p1 = sr[k1], p2 = sr[k2];
                const float u0 = __shfl_down_sync(FULLMASK, br0, 1);
                const float u1 = __shfl_down_sync(FULLMASK, br1, 1);
                const float B0 = fmaf(ba0, br2, br0 + br1);
                const float B1 = fmaf(ba1, u0, br1 + br2);
                const float B2 = fmaf(ba2, u1, br2 + u0);
                br0 = p0 * B0; br1 = p1 * B1; br2 = p2 * B2;
                if ((t & 7) == 0) bE += renorm(br0, br1, br2);
            }
            if (k == 4) {
                // beta_127 combine (no p multiply)
                const float u0 = __shfl_down_sync(FULLMASK, br0, 1);
                const float u1 = __shfl_down_sync(FULLMASK, br1, 1);
                const float B0 = fmaf(ba0, br2, br0 + br1);
                const float B1 = fmaf(ba1, u0, br1 + br2);
                const float B2 = fmaf(ba2, u1, br2 + u0);
                if (lane < 22) { exB[s0] = B0; exB[s1] = B1; exB[s2] = B2; }
                if (lane == 0) exE[1] = bE;
            }
        }
        else if (k <= 3) {
            // warps 2..7: gather stage k (fwd rows 32k.., bwd rows 224-32k..)
            gather_stage(32 * k, 224 - 32 * k, tid - 64, 192);
        }
        __syncthreads();
    }

    // ---- combine: P = sum_s alpha_127[s] * beta_127[s] ----
    if (wid == 0) {
        float part = 0.0f;
        if (lane < 22)
            part = exA[s0] * exB[s0] + exA[s1] * exB[s1] + exA[s2] * exB[s2];
#pragma unroll
        for (int o = 16; o; o >>= 1)
            part += __shfl_xor_sync(FULLMASK, part, o);
        if (lane == 0) {
            const float LN2 = 0.6931471805599453f;
            out[b] = -(logf(part) +
                       (float)(exE[0] + exE[1] - PRE_E * T_) * LN2);
        }
    }
}

extern "C" void kernel_launch(void* const* d_in, const int* in_sizes, int n_in,
                              void* d_out, int out_size)
{
    (void)n_in; (void)out_size;
    const int*   y_true;
    const float* y_pred;
    if (in_sizes[0] == B_ * L_) {
        y_true = (const int*)d_in[0];
        y_pred = (const float*)d_in[1];
    } else {
        y_true = (const int*)d_in[1];
        y_pred = (const float*)d_in[0];
    }
    ctc_fused_kernel<<<B_, 256>>>(y_true, y_pred, (float*)d_out);
}